// round 4
// baseline (speedup 1.0000x reference)
#include <cuda_runtime.h>
#include <cuda_bf16.h>
#include <cstdint>
#include <math.h>

#define NROWS 10000
#define S_    20
#define D_    512
#define DOUT_ 512
#define ATTEN_ 64

// ---------------------------------------------------------------------------
// Scratch (device globals -- no allocations allowed)
// ---------------------------------------------------------------------------
__device__ float g_neigh_sum[NROWS * D_];
__device__ float g_gates[NROWS * 2];
__device__ float g_us[D_];
__device__ float g_un[D_];

// ---------------------------------------------------------------------------
// helpers
// ---------------------------------------------------------------------------
__device__ __forceinline__ uint32_t smem_u32(const void* p) {
    uint32_t a;
    asm("{ .reg .u64 t; cvta.to.shared.u64 t, %1; cvt.u32.u64 %0, t; }" : "=r"(a) : "l"(p));
    return a;
}
__device__ __forceinline__ void split2(float a, float b, uint32_t& hi, uint32_t& lo) {
    __nv_bfloat162 h = __floats2bfloat162_rn(a, b);
    float2 hf = __bfloat1622float2(h);
    __nv_bfloat162 l = __floats2bfloat162_rn(a - hf.x, b - hf.y);
    hi = *reinterpret_cast<uint32_t*>(&h);
    lo = *reinterpret_cast<uint32_t*>(&l);
}
__device__ __forceinline__ void mma16816(float* c, const uint32_t* a, const uint32_t* b) {
    asm volatile(
        "mma.sync.aligned.m16n8k16.row.col.f32.bf16.bf16.f32 "
        "{%0,%1,%2,%3}, {%4,%5,%6,%7}, {%8,%9}, {%0,%1,%2,%3};"
        : "+f"(c[0]), "+f"(c[1]), "+f"(c[2]), "+f"(c[3])
        : "r"(a[0]), "r"(a[1]), "r"(a[2]), "r"(a[3]), "r"(b[0]), "r"(b[1]));
}
#define CP16(dst, src, pr) \
    asm volatile("cp.async.cg.shared.global [%0], [%1], 16, %2;" :: "r"(dst), "l"(src), "r"(pr))
#define CP_COMMIT() asm volatile("cp.async.commit_group;" ::: "memory")
#define CP_WAIT1()  asm volatile("cp.async.wait_group 1;" ::: "memory")
#define CP_WAIT0()  asm volatile("cp.async.wait_group 0;" ::: "memory")

// ---------------------------------------------------------------------------
// Kernel 0: u_s = self_atten @ v, u_n = neigh_atten @ v   (D=512 threads)
// ---------------------------------------------------------------------------
__global__ void prep_u(const float* __restrict__ self_atten,
                       const float* __restrict__ neigh_atten,
                       const float* __restrict__ v) {
    __shared__ float vv[ATTEN_];
    int t = threadIdx.x;
    if (t < ATTEN_) vv[t] = v[t];
    __syncthreads();
    float s = 0.f, n = 0.f;
    #pragma unroll 8
    for (int a = 0; a < ATTEN_; a++) {
        s = fmaf(self_atten[t * ATTEN_ + a],  vv[a], s);
        n = fmaf(neigh_atten[t * ATTEN_ + a], vv[a], n);
    }
    g_us[t] = s;
    g_un[t] = n;
}

// ---------------------------------------------------------------------------
// Kernel 1: neighbor softmax + reduce + per-row gate computation.
// 2 rows per block of 256 (threads [0,128) row 2b, [128,256) row 2b+1).
// ---------------------------------------------------------------------------
__global__ void reduce_gate(const float* __restrict__ neigh_vecs,
                            const float* __restrict__ neigh_weight,
                            const int*   __restrict__ neigh_column,
                            const float* __restrict__ alpha,
                            const float* __restrict__ self_vecs,
                            float*       __restrict__ neigh_sum,
                            float*       __restrict__ gates) {
    int half = threadIdx.x >> 7;
    int t    = threadIdx.x & 127;
    int row  = blockIdx.x * 2 + half;
    int lane = t & 31;

    __shared__ float se[2][S_];
    __shared__ float w[2][S_];
    __shared__ float inv[2];
    __shared__ float red[2][4][2];

    if (t < S_) se[half][t] = expf(alpha[neigh_column[row * S_ + t]]);
    __syncthreads();
    if (t == 0) {
        float s = 0.f;
        #pragma unroll
        for (int i = 0; i < S_; i++) s += se[half][i];
        inv[half] = 1.f / s;
    }
    __syncthreads();
    if (t < S_) w[half][t] = neigh_weight[row * S_ + t] * se[half][t] * inv[half];
    __syncthreads();

    const float4* nv = reinterpret_cast<const float4*>(neigh_vecs) + (size_t)row * S_ * 128;
    float4 a0 = make_float4(0.f, 0.f, 0.f, 0.f);
    float4 a1 = make_float4(0.f, 0.f, 0.f, 0.f);
    #pragma unroll
    for (int s = 0; s < S_; s += 2) {
        float4 x = nv[s * 128 + t];
        float4 y = nv[(s + 1) * 128 + t];
        float wx = w[half][s], wy = w[half][s + 1];
        a0.x = fmaf(x.x, wx, a0.x); a0.y = fmaf(x.y, wx, a0.y);
        a0.z = fmaf(x.z, wx, a0.z); a0.w = fmaf(x.w, wx, a0.w);
        a1.x = fmaf(y.x, wy, a1.x); a1.y = fmaf(y.y, wy, a1.y);
        a1.z = fmaf(y.z, wy, a1.z); a1.w = fmaf(y.w, wy, a1.w);
    }
    float4 acc = make_float4(a0.x + a1.x, a0.y + a1.y, a0.z + a1.z, a0.w + a1.w);
    reinterpret_cast<float4*>(neigh_sum)[(size_t)row * 128 + t] = acc;

    float4 un = reinterpret_cast<const float4*>(g_un)[t];
    float4 us = reinterpret_cast<const float4*>(g_us)[t];
    float4 sv = reinterpret_cast<const float4*>(self_vecs)[(size_t)row * 128 + t];
    float p = acc.x * un.x + acc.y * un.y + acc.z * un.z + acc.w * un.w;
    float q = sv.x  * us.x + sv.y  * us.y + sv.z  * us.z + sv.w  * us.w;
    #pragma unroll
    for (int o = 16; o > 0; o >>= 1) {
        p += __shfl_xor_sync(0xFFFFFFFFu, p, o);
        q += __shfl_xor_sync(0xFFFFFFFFu, q, o);
    }
    if (lane == 0) { red[half][t >> 5][0] = p; red[half][t >> 5][1] = q; }
    __syncthreads();
    if (t == 0) {
        float P = 0.f, Q = 0.f;
        #pragma unroll
        for (int i = 0; i < 4; i++) { P += red[half][i][0]; Q += red[half][i][1]; }
        float a_s = expf(tanhf(2.f * Q));
        float a_n = expf(tanhf(P + Q));
        float iv = 1.f / (a_s + a_n);
        gates[2 * row]     = a_s * iv;
        gates[2 * row + 1] = a_n * iv;
    }
}

// ---------------------------------------------------------------------------
// Kernel 2: fused dual GEMM + gated blend + relu.
//   out = relu(gs * (As@Ws) + gn * (An@Wn)), all fp32 via 3-chain bf16 split.
// Block tile 128x128, BK=32, cp.async double-buffered fp32 staging,
// bf16 split at fragment-build time. 8 warps: 4(m) x 2(n), warp tile 32x64.
// ---------------------------------------------------------------------------
__global__ void __launch_bounds__(256, 1)
gemm_fused(const float* __restrict__ As_, const float* __restrict__ An_,
           const float* __restrict__ Ws_, const float* __restrict__ Wn_,
           const float* __restrict__ gates, float* __restrict__ out, int M) {
    constexpr int K     = 512;
    constexpr int BK    = 32;
    constexpr int NITER = K / BK;        // 16
    constexpr int ASTR  = 40;            // floats per A row (32 + pad, 16B-aligned)
    constexpr int BSTR  = 132;           // floats per B k-row (128 + pad, 16B-aligned)
    constexpr int AOFFN = 128 * ASTR;    // 5120
    constexpr int BOFFS = 2 * AOFFN;     // 10240
    constexpr int BOFFN = BOFFS + 32 * BSTR; // 14464
    constexpr int STG   = BOFFN + 32 * BSTR; // 18688 floats per stage

    extern __shared__ float sm[];
    uint32_t sb = smem_u32(sm);

    int tid  = threadIdx.x;
    int lane = tid & 31, wid = tid >> 5;
    int wm   = wid & 3, wn = wid >> 2;
    int m0   = blockIdx.y * 128;
    int n0   = blockIdx.x * 128;

    float aS[2][8][4], aN[2][8][4];
    #pragma unroll
    for (int mt = 0; mt < 2; mt++)
        #pragma unroll
        for (int nt = 0; nt < 8; nt++)
            #pragma unroll
            for (int e = 0; e < 4; e++) { aS[mt][nt][e] = 0.f; aN[mt][nt][e] = 0.f; }

    auto stage = [&](int ic) {
        int p = ic & 1;
        int k0 = ic * BK;
        uint32_t base = sb + p * STG * 4;
        #pragma unroll
        for (int j = 0; j < 4; j++) {
            int c = tid + j * 256;
            int m = c >> 3, k4 = c & 7;
            int pr = (m0 + m < M) ? 16 : 0;
            int mm = (m0 + m < M) ? (m0 + m) : (M - 1);
            uint32_t dS = base + (m * ASTR + k4 * 4) * 4;
            CP16(dS,             &As_[(size_t)mm * K + k0 + k4 * 4], pr);
            CP16(dS + AOFFN * 4, &An_[(size_t)mm * K + k0 + k4 * 4], pr);
        }
        #pragma unroll
        for (int j = 0; j < 4; j++) {
            int c = tid + j * 256;
            int k = c >> 5, n4 = c & 31;
            uint32_t dS = base + (BOFFS + k * BSTR + n4 * 4) * 4;
            uint32_t dN = base + (BOFFN + k * BSTR + n4 * 4) * 4;
            CP16(dS, &Ws_[(size_t)(k0 + k) * DOUT_ + n0 + n4 * 4], 16);
            CP16(dN, &Wn_[(size_t)(k0 + k) * DOUT_ + n0 + n4 * 4], 16);
        }
    };

    auto comp = [&](int p) {
        const float* base = sm + p * STG;
        #pragma unroll
        for (int pr = 0; pr < 2; pr++) {
            const float* A = base + (pr ? AOFFN : 0);
            const float* B = base + (pr ? BOFFN : BOFFS);
            float (*acc)[8][4] = pr ? aN : aS;
            #pragma unroll
            for (int ks = 0; ks < 2; ks++) {
                int kb = ks * 16;
                uint32_t ah[2][4], al[2][4];
                #pragma unroll
                for (int mt = 0; mt < 2; mt++) {
                    int row = wm * 32 + mt * 16 + (lane >> 2);
                    int kc  = kb + (lane & 3) * 2;
                    float2 f0 = *reinterpret_cast<const float2*>(&A[row * ASTR + kc]);
                    float2 f1 = *reinterpret_cast<const float2*>(&A[(row + 8) * ASTR + kc]);
                    float2 f2 = *reinterpret_cast<const float2*>(&A[row * ASTR + kc + 8]);
                    float2 f3 = *reinterpret_cast<const float2*>(&A[(row + 8) * ASTR + kc + 8]);
                    split2(f0.x, f0.y, ah[mt][0], al[mt][0]);
                    split2(f1.x, f1.y, ah[mt][1], al[mt][1]);
                    split2(f2.x, f2.y, ah[mt][2], al[mt][2]);
                    split2(f3.x, f3.y, ah[mt][3], al[mt][3]);
                }
                uint32_t bh[8][2], bl[8][2];
                #pragma unroll
                for (int nt = 0; nt < 8; nt++) {
                    int col = wn * 64 + nt * 8 + (lane >> 2);
                    int kr  = kb + (lane & 3) * 2;
                    float b0 = B[kr * BSTR + col];
                    float b1 = B[(kr + 1) * BSTR + col];
                    float b2 = B[(kr + 8) * BSTR + col];
                    float b3 = B[(kr + 9) * BSTR + col];
                    split2(b0, b1, bh[nt][0], bl[nt][0]);
                    split2(b2, b3, bh[nt][1], bl[nt][1]);
                }
                #pragma unroll
                for (int mt = 0; mt < 2; mt++)
                    #pragma unroll
                    for (int nt = 0; nt < 8; nt++) {
                        mma16816(acc[mt][nt], ah[mt], bh[nt]);
                        mma16816(acc[mt][nt], ah[mt], bl[nt]);
                        mma16816(acc[mt][nt], al[mt], bh[nt]);
                    }
            }
        }
    };

    stage(0);
    CP_COMMIT();
    for (int ic = 0; ic < NITER; ic++) {
        if (ic + 1 < NITER) {
            stage(ic + 1);
            CP_COMMIT();
            CP_WAIT1();
        } else {
            CP_WAIT0();
        }
        __syncthreads();
        comp(ic & 1);
        __syncthreads();
    }

    // gated blend + relu epilogue, direct float2 stores
    #pragma unroll
    for (int mt = 0; mt < 2; mt++) {
        int r0 = m0 + wm * 32 + mt * 16 + (lane >> 2);
        int r1 = r0 + 8;
        float gs0 = 0.f, gn0 = 0.f, gs1 = 0.f, gn1 = 0.f;
        if (r0 < M) { gs0 = __ldg(&gates[2 * r0]); gn0 = __ldg(&gates[2 * r0 + 1]); }
        if (r1 < M) { gs1 = __ldg(&gates[2 * r1]); gn1 = __ldg(&gates[2 * r1 + 1]); }
        #pragma unroll
        for (int nt = 0; nt < 8; nt++) {
            int col = n0 + wn * 64 + nt * 8 + (lane & 3) * 2;
            if (r0 < M) {
                float2 o;
                o.x = fmaxf(fmaf(gs0, aS[mt][nt][0], gn0 * aN[mt][nt][0]), 0.f);
                o.y = fmaxf(fmaf(gs0, aS[mt][nt][1], gn0 * aN[mt][nt][1]), 0.f);
                *reinterpret_cast<float2*>(&out[(size_t)r0 * DOUT_ + col]) = o;
            }
            if (r1 < M) {
                float2 o;
                o.x = fmaxf(fmaf(gs1, aS[mt][nt][2], gn1 * aN[mt][nt][2]), 0.f);
                o.y = fmaxf(fmaf(gs1, aS[mt][nt][3], gn1 * aN[mt][nt][3]), 0.f);
                *reinterpret_cast<float2*>(&out[(size_t)r1 * DOUT_ + col]) = o;
            }
        }
    }
}

// ---------------------------------------------------------------------------
extern "C" void kernel_launch(void* const* d_in, const int* in_sizes, int n_in,
                              void* d_out, int out_size) {
    const float* self_vecs     = (const float*)d_in[0];
    const float* neigh_vecs    = (const float*)d_in[1];
    const float* neigh_weight  = (const float*)d_in[2];
    const int*   neigh_column  = (const int*)  d_in[3];
    const float* neigh_weights = (const float*)d_in[4];
    const float* self_weights  = (const float*)d_in[5];
    const float* alpha         = (const float*)d_in[6];
    const float* self_atten    = (const float*)d_in[7];
    const float* neigh_atten   = (const float*)d_in[8];
    const float* v             = (const float*)d_in[9];
    float* out = (float*)d_out;

    float *p_nsum, *p_gates;
    cudaGetSymbolAddress((void**)&p_nsum,  g_neigh_sum);
    cudaGetSymbolAddress((void**)&p_gates, g_gates);

    const int SMEM = 2 * 18688 * 4;   // 149504 bytes
    cudaFuncSetAttribute(gemm_fused, cudaFuncAttributeMaxDynamicSharedMemorySize, SMEM);

    // 0. rank-1 collapse of the attention branch
    prep_u<<<1, D_>>>(self_atten, neigh_atten, v);

    // 1. neighbor softmax + reduce + gates (2 rows / block)
    reduce_gate<<<NROWS / 2, 256>>>(neigh_vecs, neigh_weight, neigh_column,
                                    alpha, self_vecs, p_nsum, p_gates);

    // 2. fused dual GEMM + gated blend + relu
    int mblocks = (NROWS + 127) / 128;   // 79
    gemm_fused<<<dim3(DOUT_ / 128, mblocks), 256, SMEM>>>(
        self_vecs, p_nsum, self_weights, neigh_weights, p_gates, out, NROWS);
}

// round 5
// speedup vs baseline: 1.2356x; 1.2356x over previous
#include <cuda_runtime.h>
#include <cuda_bf16.h>
#include <cstdint>
#include <math.h>

#define NROWS 10000
#define S_    20
#define D_    512
#define DOUT_ 512
#define ATTEN_ 64

// ---------------------------------------------------------------------------
// Scratch (device globals -- no allocations allowed)
// ---------------------------------------------------------------------------
__device__ float g_neigh_sum[NROWS * D_];
__device__ float g_gates[NROWS * 2];
__device__ float g_us[D_];
__device__ float g_un[D_];

// ---------------------------------------------------------------------------
// helpers
// ---------------------------------------------------------------------------
__device__ __forceinline__ void split2(float a, float b, uint32_t& hi, uint32_t& lo) {
    __nv_bfloat162 h = __floats2bfloat162_rn(a, b);
    float2 hf = __bfloat1622float2(h);
    __nv_bfloat162 l = __floats2bfloat162_rn(a - hf.x, b - hf.y);
    hi = *reinterpret_cast<uint32_t*>(&h);
    lo = *reinterpret_cast<uint32_t*>(&l);
}
__device__ __forceinline__ void mma16816(float* c, const uint32_t* a, const uint32_t* b) {
    asm volatile(
        "mma.sync.aligned.m16n8k16.row.col.f32.bf16.bf16.f32 "
        "{%0,%1,%2,%3}, {%4,%5,%6,%7}, {%8,%9}, {%0,%1,%2,%3};"
        : "+f"(c[0]), "+f"(c[1]), "+f"(c[2]), "+f"(c[3])
        : "r"(a[0]), "r"(a[1]), "r"(a[2]), "r"(a[3]), "r"(b[0]), "r"(b[1]));
}

// ---------------------------------------------------------------------------
// Kernel 0: u_s = self_atten @ v, u_n = neigh_atten @ v.
// One warp per output element; coalesced over ATTEN. 64 blocks x 256 thr.
// ---------------------------------------------------------------------------
__global__ void prep_u(const float* __restrict__ self_atten,
                       const float* __restrict__ neigh_atten,
                       const float* __restrict__ v) {
    int wid  = (blockIdx.x * blockDim.x + threadIdx.x) >> 5;   // 0..511 = t
    int lane = threadIdx.x & 31;
    float v0 = v[lane], v1 = v[lane + 32];
    float s = self_atten[wid * ATTEN_ + lane]       * v0
            + self_atten[wid * ATTEN_ + lane + 32]  * v1;
    float n = neigh_atten[wid * ATTEN_ + lane]      * v0
            + neigh_atten[wid * ATTEN_ + lane + 32] * v1;
    #pragma unroll
    for (int o = 16; o > 0; o >>= 1) {
        s += __shfl_xor_sync(0xFFFFFFFFu, s, o);
        n += __shfl_xor_sync(0xFFFFFFFFu, n, o);
    }
    if (lane == 0) { g_us[wid] = s; g_un[wid] = n; }
}

// ---------------------------------------------------------------------------
// Kernel 1: neighbor softmax + reduce + per-row gates. 2 rows / 256-thr block.
// ---------------------------------------------------------------------------
__global__ void reduce_gate(const float* __restrict__ neigh_vecs,
                            const float* __restrict__ neigh_weight,
                            const int*   __restrict__ neigh_column,
                            const float* __restrict__ alpha,
                            const float* __restrict__ self_vecs,
                            float*       __restrict__ neigh_sum,
                            float*       __restrict__ gates) {
    int half = threadIdx.x >> 7;
    int t    = threadIdx.x & 127;
    int row  = blockIdx.x * 2 + half;
    int lane = t & 31;

    __shared__ float se[2][S_];
    __shared__ float w[2][S_];
    __shared__ float inv[2];
    __shared__ float red[2][4][2];

    if (t < S_) se[half][t] = expf(alpha[neigh_column[row * S_ + t]]);
    __syncthreads();
    if (t == 0) {
        float s = 0.f;
        #pragma unroll
        for (int i = 0; i < S_; i++) s += se[half][i];
        inv[half] = 1.f / s;
    }
    __syncthreads();
    if (t < S_) w[half][t] = neigh_weight[row * S_ + t] * se[half][t] * inv[half];
    __syncthreads();

    const float4* nv = reinterpret_cast<const float4*>(neigh_vecs) + (size_t)row * S_ * 128;
    float4 a0 = make_float4(0.f, 0.f, 0.f, 0.f);
    float4 a1 = make_float4(0.f, 0.f, 0.f, 0.f);
    #pragma unroll
    for (int s = 0; s < S_; s += 2) {
        float4 x = nv[s * 128 + t];
        float4 y = nv[(s + 1) * 128 + t];
        float wx = w[half][s], wy = w[half][s + 1];
        a0.x = fmaf(x.x, wx, a0.x); a0.y = fmaf(x.y, wx, a0.y);
        a0.z = fmaf(x.z, wx, a0.z); a0.w = fmaf(x.w, wx, a0.w);
        a1.x = fmaf(y.x, wy, a1.x); a1.y = fmaf(y.y, wy, a1.y);
        a1.z = fmaf(y.z, wy, a1.z); a1.w = fmaf(y.w, wy, a1.w);
    }
    float4 acc = make_float4(a0.x + a1.x, a0.y + a1.y, a0.z + a1.z, a0.w + a1.w);
    reinterpret_cast<float4*>(neigh_sum)[(size_t)row * 128 + t] = acc;

    float4 un = reinterpret_cast<const float4*>(g_un)[t];
    float4 us = reinterpret_cast<const float4*>(g_us)[t];
    float4 sv = reinterpret_cast<const float4*>(self_vecs)[(size_t)row * 128 + t];
    float p = acc.x * un.x + acc.y * un.y + acc.z * un.z + acc.w * un.w;
    float q = sv.x  * us.x + sv.y  * us.y + sv.z  * us.z + sv.w  * us.w;
    #pragma unroll
    for (int o = 16; o > 0; o >>= 1) {
        p += __shfl_xor_sync(0xFFFFFFFFu, p, o);
        q += __shfl_xor_sync(0xFFFFFFFFu, q, o);
    }
    if (lane == 0) { red[half][t >> 5][0] = p; red[half][t >> 5][1] = q; }
    __syncthreads();
    if (t == 0) {
        float P = 0.f, Q = 0.f;
        #pragma unroll
        for (int i = 0; i < 4; i++) { P += red[half][i][0]; Q += red[half][i][1]; }
        float a_s = expf(tanhf(2.f * Q));
        float a_n = expf(tanhf(P + Q));
        float iv = 1.f / (a_s + a_n);
        gates[2 * row]     = a_s * iv;
        gates[2 * row + 1] = a_n * iv;
    }
}

// ---------------------------------------------------------------------------
// Kernel 2: fused dual GEMM + gated blend + relu.
//   out = relu(gs*(As@Ws) + gn*(An@Wn)), 3-chain bf16 split, fp32 accum.
// Block tile 128x64 covering BOTH problems; 8 warps 4(m)x2(n), warp 32x32.
// bf16 hi/lo staged in smem (split once); reg-pipelined double buffer.
// ---------------------------------------------------------------------------
__global__ void __launch_bounds__(256, 1)
gemm_fused(const float* __restrict__ As_, const float* __restrict__ An_,
           const float* __restrict__ Ws_, const float* __restrict__ Wn_,
           const float* __restrict__ gates, float* __restrict__ out, int M) {
    constexpr int K     = 512;
    constexpr int BK    = 32;
    constexpr int NITER = K / BK;          // 16
    constexpr int BN    = 64;
    constexpr int ASTR  = 20;              // u32 per A row (16 pairs + 4 pad)
    constexpr int APART = 128 * ASTR;      // 2560 u32 per (problem, part)
    constexpr int BSTR  = BN + 8;          // 72 u32 per k2-row
    constexpr int BPART = 16 * BSTR;       // 1152 u32
    constexpr int BBASE = 4 * APART;       // 10240
    constexpr int STG   = BBASE + 4 * BPART;  // 14848 u32 / stage

    extern __shared__ uint32_t s32[];

    int tid  = threadIdx.x;
    int lane = tid & 31, wid = tid >> 5;
    int wm   = wid & 3, wn = wid >> 2;
    int m0   = blockIdx.y * 128;
    int n0   = blockIdx.x * BN;

    float aS[2][4][4], aN[2][4][4];
    #pragma unroll
    for (int mt = 0; mt < 2; mt++)
        #pragma unroll
        for (int nt = 0; nt < 4; nt++)
            #pragma unroll
            for (int e = 0; e < 4; e++) { aS[mt][nt][e] = 0.f; aN[mt][nt][e] = 0.f; }

    float4 areg[2][4];                 // [problem][j]
    float4 b0reg[2], b1reg[2];         // [problem]

    auto load_gmem = [&](int ic) {
        int k0 = ic * BK;
        #pragma unroll
        for (int j = 0; j < 4; j++) {
            int s = tid + j * 256;
            int m = s >> 3, k4 = s & 7;
            bool ok = (m0 + m < M);
            size_t off = (size_t)(ok ? m0 + m : 0) * K + k0 + k4 * 4;
            areg[0][j] = ok ? *reinterpret_cast<const float4*>(&As_[off]) : make_float4(0,0,0,0);
            areg[1][j] = ok ? *reinterpret_cast<const float4*>(&An_[off]) : make_float4(0,0,0,0);
        }
        {
            int k2 = tid >> 4, n4 = tid & 15;
            size_t g0 = (size_t)(k0 + 2 * k2)     * DOUT_ + n0 + n4 * 4;
            size_t g1 = (size_t)(k0 + 2 * k2 + 1) * DOUT_ + n0 + n4 * 4;
            b0reg[0] = *reinterpret_cast<const float4*>(&Ws_[g0]);
            b1reg[0] = *reinterpret_cast<const float4*>(&Ws_[g1]);
            b0reg[1] = *reinterpret_cast<const float4*>(&Wn_[g0]);
            b1reg[1] = *reinterpret_cast<const float4*>(&Wn_[g1]);
        }
    };

    auto store_smem = [&](int p) {
        uint32_t* base = s32 + p * STG;
        #pragma unroll
        for (int pr = 0; pr < 2; pr++) {
            uint32_t* AH = base + pr * 2 * APART;
            uint32_t* AL = AH + APART;
            #pragma unroll
            for (int j = 0; j < 4; j++) {
                int s = tid + j * 256;
                int m = s >> 3, k2 = (s & 7) * 2;
                uint32_t h0, l0, h1, l1;
                split2(areg[pr][j].x, areg[pr][j].y, h0, l0);
                split2(areg[pr][j].z, areg[pr][j].w, h1, l1);
                AH[m * ASTR + k2]     = h0;
                AH[m * ASTR + k2 + 1] = h1;
                AL[m * ASTR + k2]     = l0;
                AL[m * ASTR + k2 + 1] = l1;
            }
            uint32_t* BH = base + BBASE + pr * 2 * BPART;
            uint32_t* BL = BH + BPART;
            int k2 = tid >> 4, n4 = tid & 15;
            uint32_t ph[4], pl[4];
            split2(b0reg[pr].x, b1reg[pr].x, ph[0], pl[0]);
            split2(b0reg[pr].y, b1reg[pr].y, ph[1], pl[1]);
            split2(b0reg[pr].z, b1reg[pr].z, ph[2], pl[2]);
            split2(b0reg[pr].w, b1reg[pr].w, ph[3], pl[3]);
            *reinterpret_cast<uint4*>(&BH[k2 * BSTR + n4 * 4]) = make_uint4(ph[0], ph[1], ph[2], ph[3]);
            *reinterpret_cast<uint4*>(&BL[k2 * BSTR + n4 * 4]) = make_uint4(pl[0], pl[1], pl[2], pl[3]);
        }
    };

    auto compute = [&](int p) {
        const uint32_t* base = s32 + p * STG;
        #pragma unroll
        for (int pr = 0; pr < 2; pr++) {
            const uint32_t* AH = base + pr * 2 * APART;
            const uint32_t* AL = AH + APART;
            const uint32_t* BH = base + BBASE + pr * 2 * BPART;
            const uint32_t* BL = BH + BPART;
            float (*acc)[4][4] = pr ? aN : aS;
            #pragma unroll
            for (int ch = 0; ch < 3; ch++) {
                const uint32_t* Ax = (ch == 2) ? AL : AH;
                const uint32_t* Bx = (ch == 1) ? BL : BH;
                #pragma unroll
                for (int ks = 0; ks < 2; ks++) {
                    int base8 = ks * 8;
                    uint32_t af[2][4];
                    #pragma unroll
                    for (int mt = 0; mt < 2; mt++) {
                        int row = wm * 32 + mt * 16 + (lane >> 2);
                        int kc  = base8 + (lane & 3);
                        af[mt][0] = Ax[row * ASTR + kc];
                        af[mt][1] = Ax[(row + 8) * ASTR + kc];
                        af[mt][2] = Ax[row * ASTR + kc + 4];
                        af[mt][3] = Ax[(row + 8) * ASTR + kc + 4];
                    }
                    uint32_t bf[4][2];
                    #pragma unroll
                    for (int nt = 0; nt < 4; nt++) {
                        int col = wn * 32 + nt * 8 + (lane >> 2);
                        int kc  = base8 + (lane & 3);
                        bf[nt][0] = Bx[kc * BSTR + col];
                        bf[nt][1] = Bx[(kc + 4) * BSTR + col];
                    }
                    #pragma unroll
                    for (int mt = 0; mt < 2; mt++)
                        #pragma unroll
                        for (int nt = 0; nt < 4; nt++)
                            mma16816(acc[mt][nt], af[mt], bf[nt]);
                }
            }
        }
    };

    load_gmem(0);
    store_smem(0);
    __syncthreads();
    for (int ic = 0; ic < NITER; ic++) {
        if (ic + 1 < NITER) load_gmem(ic + 1);
        compute(ic & 1);
        if (ic + 1 < NITER) store_smem((ic + 1) & 1);
        __syncthreads();
    }

    // fused gate + blend + relu epilogue
    #pragma unroll
    for (int mt = 0; mt < 2; mt++) {
        int r0 = m0 + wm * 32 + mt * 16 + (lane >> 2);
        int r1 = r0 + 8;
        float gs0 = 0.f, gn0 = 0.f, gs1 = 0.f, gn1 = 0.f;
        if (r0 < M) { gs0 = __ldg(&gates[2 * r0]); gn0 = __ldg(&gates[2 * r0 + 1]); }
        if (r1 < M) { gs1 = __ldg(&gates[2 * r1]); gn1 = __ldg(&gates[2 * r1 + 1]); }
        #pragma unroll
        for (int nt = 0; nt < 4; nt++) {
            int col = n0 + wn * 32 + nt * 8 + (lane & 3) * 2;
            if (r0 < M) {
                float2 o;
                o.x = fmaxf(fmaf(gs0, aS[mt][nt][0], gn0 * aN[mt][nt][0]), 0.f);
                o.y = fmaxf(fmaf(gs0, aS[mt][nt][1], gn0 * aN[mt][nt][1]), 0.f);
                *reinterpret_cast<float2*>(&out[(size_t)r0 * DOUT_ + col]) = o;
            }
            if (r1 < M) {
                float2 o;
                o.x = fmaxf(fmaf(gs1, aS[mt][nt][2], gn1 * aN[mt][nt][2]), 0.f);
                o.y = fmaxf(fmaf(gs1, aS[mt][nt][3], gn1 * aN[mt][nt][3]), 0.f);
                *reinterpret_cast<float2*>(&out[(size_t)r1 * DOUT_ + col]) = o;
            }
        }
    }
}

// ---------------------------------------------------------------------------
extern "C" void kernel_launch(void* const* d_in, const int* in_sizes, int n_in,
                              void* d_out, int out_size) {
    const float* self_vecs     = (const float*)d_in[0];
    const float* neigh_vecs    = (const float*)d_in[1];
    const float* neigh_weight  = (const float*)d_in[2];
    const int*   neigh_column  = (const int*)  d_in[3];
    const float* neigh_weights = (const float*)d_in[4];
    const float* self_weights  = (const float*)d_in[5];
    const float* alpha         = (const float*)d_in[6];
    const float* self_atten    = (const float*)d_in[7];
    const float* neigh_atten   = (const float*)d_in[8];
    const float* v             = (const float*)d_in[9];
    float* out = (float*)d_out;

    float *p_nsum, *p_gates;
    cudaGetSymbolAddress((void**)&p_nsum,  g_neigh_sum);
    cudaGetSymbolAddress((void**)&p_gates, g_gates);

    const int SMEM = 2 * 14848 * 4;   // 118784 bytes
    cudaFuncSetAttribute(gemm_fused, cudaFuncAttributeMaxDynamicSharedMemorySize, SMEM);

    // 0. rank-1 collapse of attention branch (coalesced, 512 warps)
    prep_u<<<64, 256>>>(self_atten, neigh_atten, v);

    // 1. neighbor softmax + reduce + gates
    reduce_gate<<<NROWS / 2, 256>>>(neigh_vecs, neigh_weight, neigh_column,
                                    alpha, self_vecs, p_nsum, p_gates);

    // 2. fused dual GEMM + gated blend + relu
    int mblocks = (NROWS + 127) / 128;   // 79
    gemm_fused<<<dim3(DOUT_ / 64, mblocks), 256, SMEM>>>(
        self_vecs, p_nsum, self_weights, neigh_weights, p_gates, out, NROWS);
}

// round 6
// speedup vs baseline: 1.3241x; 1.0716x over previous
#include <cuda_runtime.h>
#include <cuda_bf16.h>
#include <cstdint>
#include <math.h>

#define NROWS 10000
#define S_    20
#define D_    512
#define DOUT_ 512
#define ATTEN_ 64

// ---------------------------------------------------------------------------
// Scratch (device globals -- no allocations allowed)
// ---------------------------------------------------------------------------
__device__ float g_neigh_sum[NROWS * D_];
__device__ float g_from_self[NROWS * DOUT_];
__device__ float g_gates[NROWS * 2];
__device__ float g_us[D_];
__device__ float g_un[D_];

// GEMM geometry (shared by both GEMM bodies)
#define GK     512
#define GBK    32
#define GNITER (GK / GBK)        // 16
#define GBN    64
#define ASTR   20                // u32 per A row (16 bf16x2 + 4 pad)
#define APART  (128 * ASTR)      // 2560
#define BSTR   (GBN + 8)         // 72
#define BPART  (16 * BSTR)       // 1152
#define GBB    (2 * APART)       // B base: 5120
#define GSTG   (GBB + 2 * BPART) // 7424 u32 per stage
#define GSMEM  (2 * GSTG * 4)    // 59392 bytes

// ---------------------------------------------------------------------------
// helpers
// ---------------------------------------------------------------------------
__device__ __forceinline__ void split2(float a, float b, uint32_t& hi, uint32_t& lo) {
    __nv_bfloat162 h = __floats2bfloat162_rn(a, b);
    float2 hf = __bfloat1622float2(h);
    __nv_bfloat162 l = __floats2bfloat162_rn(a - hf.x, b - hf.y);
    hi = *reinterpret_cast<uint32_t*>(&h);
    lo = *reinterpret_cast<uint32_t*>(&l);
}
__device__ __forceinline__ void mma16816(float* c, const uint32_t* a, const uint32_t* b) {
    asm volatile(
        "mma.sync.aligned.m16n8k16.row.col.f32.bf16.bf16.f32 "
        "{%0,%1,%2,%3}, {%4,%5,%6,%7}, {%8,%9}, {%0,%1,%2,%3};"
        : "+f"(c[0]), "+f"(c[1]), "+f"(c[2]), "+f"(c[3])
        : "r"(a[0]), "r"(a[1]), "r"(a[2]), "r"(a[3]), "r"(b[0]), "r"(b[1]));
}

// ---------------------------------------------------------------------------
// Single-problem 128x64 bf16-split GEMM body (3 chains, fp32 accum).
// acc produced in registers; caller-provided epilogue semantics via flag.
// ---------------------------------------------------------------------------
struct GemmAcc { float a[2][4][4]; };

__device__ __forceinline__ void gemm_body(
    const float* __restrict__ A_, const float* __restrict__ W_,
    uint32_t* s32, int m0, int n0, int M, GemmAcc& R) {

    int tid  = threadIdx.x;
    int lane = tid & 31, wid = tid >> 5;
    int wm   = wid & 3, wn = wid >> 2;

    #pragma unroll
    for (int mt = 0; mt < 2; mt++)
        #pragma unroll
        for (int nt = 0; nt < 4; nt++)
            #pragma unroll
            for (int e = 0; e < 4; e++) R.a[mt][nt][e] = 0.f;

    float4 areg[4];
    float4 b0reg, b1reg;

    auto load_gmem = [&](int ic) {
        int k0 = ic * GBK;
        #pragma unroll
        for (int j = 0; j < 4; j++) {
            int s = tid + j * 256;
            int m = s >> 3, k4 = s & 7;
            bool ok = (m0 + m < M);
            size_t off = (size_t)(ok ? m0 + m : 0) * GK + k0 + k4 * 4;
            areg[j] = ok ? *reinterpret_cast<const float4*>(&A_[off]) : make_float4(0,0,0,0);
        }
        int k2 = tid >> 4, n4 = tid & 15;
        b0reg = *reinterpret_cast<const float4*>(&W_[(size_t)(k0 + 2 * k2)     * DOUT_ + n0 + n4 * 4]);
        b1reg = *reinterpret_cast<const float4*>(&W_[(size_t)(k0 + 2 * k2 + 1) * DOUT_ + n0 + n4 * 4]);
    };

    auto store_smem = [&](int p) {
        uint32_t* base = s32 + p * GSTG;
        uint32_t* AH = base;
        uint32_t* AL = base + APART;
        #pragma unroll
        for (int j = 0; j < 4; j++) {
            int s = tid + j * 256;
            int m = s >> 3, k2 = (s & 7) * 2;
            uint32_t h0, l0, h1, l1;
            split2(areg[j].x, areg[j].y, h0, l0);
            split2(areg[j].z, areg[j].w, h1, l1);
            AH[m * ASTR + k2]     = h0;
            AH[m * ASTR + k2 + 1] = h1;
            AL[m * ASTR + k2]     = l0;
            AL[m * ASTR + k2 + 1] = l1;
        }
        uint32_t* BH = base + GBB;
        uint32_t* BL = BH + BPART;
        int k2 = tid >> 4, n4 = tid & 15;
        uint32_t ph[4], pl[4];
        split2(b0reg.x, b1reg.x, ph[0], pl[0]);
        split2(b0reg.y, b1reg.y, ph[1], pl[1]);
        split2(b0reg.z, b1reg.z, ph[2], pl[2]);
        split2(b0reg.w, b1reg.w, ph[3], pl[3]);
        *reinterpret_cast<uint4*>(&BH[k2 * BSTR + n4 * 4]) = make_uint4(ph[0], ph[1], ph[2], ph[3]);
        *reinterpret_cast<uint4*>(&BL[k2 * BSTR + n4 * 4]) = make_uint4(pl[0], pl[1], pl[2], pl[3]);
    };

    auto compute = [&](int p) {
        const uint32_t* base = s32 + p * GSTG;
        const uint32_t* AH = base;
        const uint32_t* AL = base + APART;
        const uint32_t* BH = base + GBB;
        const uint32_t* BL = BH + BPART;
        #pragma unroll
        for (int ch = 0; ch < 3; ch++) {
            const uint32_t* Ax = (ch == 2) ? AL : AH;
            const uint32_t* Bx = (ch == 1) ? BL : BH;
            #pragma unroll
            for (int ks = 0; ks < 2; ks++) {
                int b8 = ks * 8;
                uint32_t af[2][4];
                #pragma unroll
                for (int mt = 0; mt < 2; mt++) {
                    int row = wm * 32 + mt * 16 + (lane >> 2);
                    int kc  = b8 + (lane & 3);
                    af[mt][0] = Ax[row * ASTR + kc];
                    af[mt][1] = Ax[(row + 8) * ASTR + kc];
                    af[mt][2] = Ax[row * ASTR + kc + 4];
                    af[mt][3] = Ax[(row + 8) * ASTR + kc + 4];
                }
                uint32_t bf[4][2];
                #pragma unroll
                for (int nt = 0; nt < 4; nt++) {
                    int col = wn * 32 + nt * 8 + (lane >> 2);
                    int kc  = b8 + (lane & 3);
                    bf[nt][0] = Bx[kc * BSTR + col];
                    bf[nt][1] = Bx[(kc + 4) * BSTR + col];
                }
                #pragma unroll
                for (int mt = 0; mt < 2; mt++)
                    #pragma unroll
                    for (int nt = 0; nt < 4; nt++)
                        mma16816(R.a[mt][nt], af[mt], bf[nt]);
            }
        }
    };

    load_gmem(0);
    store_smem(0);
    __syncthreads();
    for (int ic = 0; ic < GNITER; ic++) {
        if (ic + 1 < GNITER) load_gmem(ic + 1);
        compute(ic & 1);
        if (ic + 1 < GNITER) store_smem((ic + 1) & 1);
        __syncthreads();
    }
}

// ---------------------------------------------------------------------------
// Kernel 0: u_s = self_atten @ v, u_n = neigh_atten @ v (one warp / element)
// ---------------------------------------------------------------------------
__global__ void prep_u(const float* __restrict__ self_atten,
                       const float* __restrict__ neigh_atten,
                       const float* __restrict__ v) {
    int wid  = (blockIdx.x * blockDim.x + threadIdx.x) >> 5;
    int lane = threadIdx.x & 31;
    float v0 = v[lane], v1 = v[lane + 32];
    float s = self_atten[wid * ATTEN_ + lane]       * v0
            + self_atten[wid * ATTEN_ + lane + 32]  * v1;
    float n = neigh_atten[wid * ATTEN_ + lane]      * v0
            + neigh_atten[wid * ATTEN_ + lane + 32] * v1;
    #pragma unroll
    for (int o = 16; o > 0; o >>= 1) {
        s += __shfl_xor_sync(0xFFFFFFFFu, s, o);
        n += __shfl_xor_sync(0xFFFFFFFFu, n, o);
    }
    if (lane == 0) { g_us[wid] = s; g_un[wid] = n; }
}

// ---------------------------------------------------------------------------
// Mega kernel: interleaved roles.
//   blockIdx.x % 9 == 4  -> self-GEMM block (writes raw As@Ws to g_from_self)
//   otherwise            -> reduce+gate block (2 rows each)
// ---------------------------------------------------------------------------
__global__ void __launch_bounds__(256)
mega_kernel(const float* __restrict__ neigh_vecs,
            const float* __restrict__ neigh_weight,
            const int*   __restrict__ neigh_column,
            const float* __restrict__ alpha,
            const float* __restrict__ self_vecs,
            const float* __restrict__ self_weights,
            int M) {
    extern __shared__ uint32_t s32[];
    int rem = blockIdx.x % 9;

    if (rem == 4) {
        // ------- self GEMM role -------
        int g  = blockIdx.x / 9;               // 0..631
        int n0 = (g & 7) * GBN;
        int m0 = (g >> 3) * 128;
        GemmAcc R;
        gemm_body(self_vecs, self_weights, s32, m0, n0, M, R);

        int lane = threadIdx.x & 31, wid = threadIdx.x >> 5;
        int wm = wid & 3, wn = wid >> 2;
        #pragma unroll
        for (int mt = 0; mt < 2; mt++) {
            int r0 = m0 + wm * 32 + mt * 16 + (lane >> 2);
            int r1 = r0 + 8;
            #pragma unroll
            for (int nt = 0; nt < 4; nt++) {
                int col = n0 + wn * 32 + nt * 8 + (lane & 3) * 2;
                if (r0 < M)
                    *reinterpret_cast<float2*>(&g_from_self[(size_t)r0 * DOUT_ + col]) =
                        make_float2(R.a[mt][nt][0], R.a[mt][nt][1]);
                if (r1 < M)
                    *reinterpret_cast<float2*>(&g_from_self[(size_t)r1 * DOUT_ + col]) =
                        make_float2(R.a[mt][nt][2], R.a[mt][nt][3]);
            }
        }
        return;
    }

    // ------- reduce + gate role -------
    int rb = (blockIdx.x / 9) * 8 + (rem < 4 ? rem : rem - 1);
    if (rb >= NROWS / 2) return;

    float* sred = reinterpret_cast<float*>(s32);
    // layout: se[2][20] | w[2][20] | inv[2] | red[2][4][2]
    float* se  = sred;
    float* wv  = sred + 40;
    float* inv = sred + 80;
    float* red = sred + 82;

    int half = threadIdx.x >> 7;
    int t    = threadIdx.x & 127;
    int row  = rb * 2 + half;
    int lane = t & 31;

    if (t < S_) se[half * S_ + t] = expf(alpha[neigh_column[row * S_ + t]]);
    __syncthreads();
    if (t == 0) {
        float s = 0.f;
        #pragma unroll
        for (int i = 0; i < S_; i++) s += se[half * S_ + i];
        inv[half] = 1.f / s;
    }
    __syncthreads();
    if (t < S_) wv[half * S_ + t] = neigh_weight[row * S_ + t] * se[half * S_ + t] * inv[half];
    __syncthreads();

    const float4* nv = reinterpret_cast<const float4*>(neigh_vecs) + (size_t)row * S_ * 128;
    float4 a0 = make_float4(0.f, 0.f, 0.f, 0.f);
    float4 a1 = make_float4(0.f, 0.f, 0.f, 0.f);
    #pragma unroll
    for (int s = 0; s < S_; s += 2) {
        float4 x = nv[s * 128 + t];
        float4 y = nv[(s + 1) * 128 + t];
        float wx = wv[half * S_ + s], wy = wv[half * S_ + s + 1];
        a0.x = fmaf(x.x, wx, a0.x); a0.y = fmaf(x.y, wx, a0.y);
        a0.z = fmaf(x.z, wx, a0.z); a0.w = fmaf(x.w, wx, a0.w);
        a1.x = fmaf(y.x, wy, a1.x); a1.y = fmaf(y.y, wy, a1.y);
        a1.z = fmaf(y.z, wy, a1.z); a1.w = fmaf(y.w, wy, a1.w);
    }
    float4 acc = make_float4(a0.x + a1.x, a0.y + a1.y, a0.z + a1.z, a0.w + a1.w);
    reinterpret_cast<float4*>(g_neigh_sum)[(size_t)row * 128 + t] = acc;

    float4 un = reinterpret_cast<const float4*>(g_un)[t];
    float4 us = reinterpret_cast<const float4*>(g_us)[t];
    float4 sv = reinterpret_cast<const float4*>(self_vecs)[(size_t)row * 128 + t];
    float p = acc.x * un.x + acc.y * un.y + acc.z * un.z + acc.w * un.w;
    float q = sv.x  * us.x + sv.y  * us.y + sv.z  * us.z + sv.w  * us.w;
    #pragma unroll
    for (int o = 16; o > 0; o >>= 1) {
        p += __shfl_xor_sync(0xFFFFFFFFu, p, o);
        q += __shfl_xor_sync(0xFFFFFFFFu, q, o);
    }
    if (lane == 0) { red[(half * 4 + (t >> 5)) * 2] = p; red[(half * 4 + (t >> 5)) * 2 + 1] = q; }
    __syncthreads();
    if (t == 0) {
        float P = 0.f, Q = 0.f;
        #pragma unroll
        for (int i = 0; i < 4; i++) { P += red[(half * 4 + i) * 2]; Q += red[(half * 4 + i) * 2 + 1]; }
        float a_s = expf(tanhf(2.f * Q));
        float a_n = expf(tanhf(P + Q));
        float iv = 1.f / (a_s + a_n);
        g_gates[2 * row]     = a_s * iv;
        g_gates[2 * row + 1] = a_n * iv;
    }
}

// ---------------------------------------------------------------------------
// Kernel 2: neigh GEMM + gated blend with g_from_self + relu -> out
// ---------------------------------------------------------------------------
__global__ void __launch_bounds__(256)
gemm_neigh_blend(const float* __restrict__ An_, const float* __restrict__ Wn_,
                 float* __restrict__ out, int M) {
    extern __shared__ uint32_t s32[];
    int m0 = blockIdx.y * 128;
    int n0 = blockIdx.x * GBN;
    GemmAcc R;
    gemm_body(An_, Wn_, s32, m0, n0, M, R);

    int lane = threadIdx.x & 31, wid = threadIdx.x >> 5;
    int wm = wid & 3, wn = wid >> 2;
    #pragma unroll
    for (int mt = 0; mt < 2; mt++) {
        int r0 = m0 + wm * 32 + mt * 16 + (lane >> 2);
        int r1 = r0 + 8;
        float gs0 = 0.f, gn0 = 0.f, gs1 = 0.f, gn1 = 0.f;
        if (r0 < M) { gs0 = __ldg(&g_gates[2 * r0]); gn0 = __ldg(&g_gates[2 * r0 + 1]); }
        if (r1 < M) { gs1 = __ldg(&g_gates[2 * r1]); gn1 = __ldg(&g_gates[2 * r1 + 1]); }
        #pragma unroll
        for (int nt = 0; nt < 4; nt++) {
            int col = n0 + wn * 32 + nt * 8 + (lane & 3) * 2;
            if (r0 < M) {
                float2 fs = *reinterpret_cast<const float2*>(&g_from_self[(size_t)r0 * DOUT_ + col]);
                float2 o;
                o.x = fmaxf(fmaf(gs0, fs.x, gn0 * R.a[mt][nt][0]), 0.f);
                o.y = fmaxf(fmaf(gs0, fs.y, gn0 * R.a[mt][nt][1]), 0.f);
                *reinterpret_cast<float2*>(&out[(size_t)r0 * DOUT_ + col]) = o;
            }
            if (r1 < M) {
                float2 fs = *reinterpret_cast<const float2*>(&g_from_self[(size_t)r1 * DOUT_ + col]);
                float2 o;
                o.x = fmaxf(fmaf(gs1, fs.x, gn1 * R.a[mt][nt][2]), 0.f);
                o.y = fmaxf(fmaf(gs1, fs.y, gn1 * R.a[mt][nt][3]), 0.f);
                *reinterpret_cast<float2*>(&out[(size_t)r1 * DOUT_ + col]) = o;
            }
        }
    }
}

// ---------------------------------------------------------------------------
extern "C" void kernel_launch(void* const* d_in, const int* in_sizes, int n_in,
                              void* d_out, int out_size) {
    const float* self_vecs     = (const float*)d_in[0];
    const float* neigh_vecs    = (const float*)d_in[1];
    const float* neigh_weight  = (const float*)d_in[2];
    const int*   neigh_column  = (const int*)  d_in[3];
    const float* neigh_weights = (const float*)d_in[4];
    const float* self_weights  = (const float*)d_in[5];
    const float* alpha         = (const float*)d_in[6];
    const float* self_atten    = (const float*)d_in[7];
    const float* neigh_atten   = (const float*)d_in[8];
    const float* v             = (const float*)d_in[9];
    float* out = (float*)d_out;

    float* p_nsum;
    cudaGetSymbolAddress((void**)&p_nsum, g_neigh_sum);

    cudaFuncSetAttribute(mega_kernel,      cudaFuncAttributeMaxDynamicSharedMemorySize, GSMEM);
    cudaFuncSetAttribute(gemm_neigh_blend, cudaFuncAttributeMaxDynamicSharedMemorySize, GSMEM);

    // 0. rank-1 collapse of attention branch
    prep_u<<<64, 256>>>(self_atten, neigh_atten, v);

    // 1. overlapped reduce+gate (5056 role-blocks) and self-GEMM (632 role-blocks)
    //    grid = 632 * 9 = 5688, every 9th block (rem 4) is a GEMM block.
    mega_kernel<<<5688, 256, GSMEM>>>(neigh_vecs, neigh_weight, neigh_column,
                                      alpha, self_vecs, self_weights, NROWS);

    // 2. neigh GEMM + gated blend + relu
    gemm_neigh_blend<<<dim3(DOUT_ / GBN, (NROWS + 127) / 128), 256, GSMEM>>>(
        p_nsum, neigh_weights, out, NROWS);
}